// round 6
// baseline (speedup 1.0000x reference)
#include <cuda_runtime.h>
#include <cstdint>

namespace {
constexpr int Bb = 4, Nn = 16, Tt = 2048, Ff = 512, NC = 43;
constexpr int BT = Bb * Tt;  // 8192
}

// ---------------- scratch (device globals; no allocation allowed) ------------
__device__ float g_table2[NC * Ff];
__device__ float g_Wc[Ff * 4];
__device__ float g_W2r[Ff * Ff];                    // tf32-rounded W2
__device__ float g_Wm2[Ff * Nn * Ff];               // tf32-rounded Wm^T [f][n][c]
__device__ float g_Y[(long long)BT * Nn * Ff];      // 256MB (tf32-rounded)
__device__ float g_node2[(long long)BT * Nn * Ff];  // 256MB (tf32-rounded)
__device__ float g_feat[(long long)BT * Ff];        // 16MB (full fp32)

// ---------------- helpers -----------------------------------------------------
__device__ __forceinline__ uint32_t smem_u32(const void* p) {
    uint32_t a;
    asm("{ .reg .u64 t; cvta.to.shared.u64 t, %1; cvt.u32.u64 %0, t; }" : "=r"(a) : "l"(p));
    return a;
}
__device__ __forceinline__ void cpa16(uint32_t s, const void* g) {
    asm volatile("cp.async.cg.shared.global [%0], [%1], 16;" :: "r"(s), "l"(g) : "memory");
}
__device__ __forceinline__ float tf32r(float x) {
    uint32_t r;
    asm("cvt.rna.tf32.f32 %0, %1;" : "=r"(r) : "f"(x));
    return __uint_as_float(r);
}
__device__ __forceinline__ void mma_tf32(float* c, const uint32_t* a, const uint32_t* b) {
    asm volatile(
        "mma.sync.aligned.m16n8k8.row.col.f32.tf32.tf32.f32 "
        "{%0,%1,%2,%3}, {%4,%5,%6,%7}, {%8,%9}, {%0,%1,%2,%3};"
        : "+f"(c[0]), "+f"(c[1]), "+f"(c[2]), "+f"(c[3])
        : "r"(a[0]), "r"(a[1]), "r"(a[2]), "r"(a[3]), "r"(b[0]), "r"(b[1]));
}

// ---------------- precompute: table2 = W1a@emb^T, Wc = W1b@W_lin -------------
__global__ void kprep(const float* __restrict__ W1, const float* __restrict__ emb,
                      const float* __restrict__ Wlin) {
    __shared__ float se[Ff];
    __shared__ float sw[Ff * 4];
    int f = threadIdx.x;
    int c = blockIdx.x;
    if (c < NC) {
        se[f] = emb[c * Ff + f];
        __syncthreads();
        float s = 0.f;
        const float* w = W1 + (size_t)f * (2 * Ff);
        #pragma unroll 8
        for (int k = 0; k < Ff; k++) s = fmaf(w[k], se[k], s);
        g_table2[c * Ff + f] = s;
    } else {
        #pragma unroll
        for (int q = 0; q < 4; q++) sw[f + q * Ff] = Wlin[f + q * Ff];
        __syncthreads();
        float s0 = 0.f, s1 = 0.f, s2 = 0.f, s3 = 0.f;
        const float* w = W1 + (size_t)f * (2 * Ff) + Ff;
        #pragma unroll 4
        for (int k = 0; k < Ff; k++) {
            float v = w[k];
            s0 = fmaf(v, sw[k * 4 + 0], s0);
            s1 = fmaf(v, sw[k * 4 + 1], s1);
            s2 = fmaf(v, sw[k * 4 + 2], s2);
            s3 = fmaf(v, sw[k * 4 + 3], s3);
        }
        g_Wc[f * 4 + 0] = s0; g_Wc[f * 4 + 1] = s1;
        g_Wc[f * 4 + 2] = s2; g_Wc[f * 4 + 3] = s3;
    }
}

// ---------------- precompute: Wm2[f][n][c] = tf32(Wm[f][c][n]), W2r = tf32(W2)
__global__ void ktrans(const float* __restrict__ Wm) {
    int idx = blockIdx.x * 1024 + threadIdx.x;
    int c = idx & (Ff - 1);
    int n = (idx >> 9) & (Nn - 1);
    int f = idx >> 13;
    g_Wm2[idx] = tf32r(Wm[((size_t)f * Ff + c) * Nn + n]);
}
__global__ void kw2(const float* __restrict__ W2) {
    int i = blockIdx.x * 1024 + threadIdx.x;
    g_W2r[i] = tf32r(W2[i]);
}

// ---------------- stage 1: lookups + two 16x16 em matmuls -> Y (tf32-rounded)
__global__ void __launch_bounds__(512, 3)
k1(const float* __restrict__ bbox, const int* __restrict__ cls,
   const float* __restrict__ edge) {
    int bt = blockIdx.x;
    int b = bt >> 11, t = bt & (Tt - 1);
    __shared__ float em[Nn][Nn];
    __shared__ int   scls[Nn];
    __shared__ float sbb[Nn][4];
    int tid = threadIdx.x;   // 512
    if (tid < 256) {
        int i = tid >> 4, j = tid & 15;
        em[i][j] = edge[((size_t)(b * Nn + i) * Nn + j) * Tt + t];
    }
    if (tid >= 256 && tid < 256 + Nn)
        scls[tid - 256] = cls[(size_t)(b * Nn + tid - 256) * Tt + t];
    if (tid >= 320 && tid < 320 + Nn * 4) {
        int q = tid - 320;
        int j = q >> 2, c = q & 3;
        sbb[j][c] = bbox[((size_t)(b * Nn + j) * 4 + c) * Tt + t];
    }
    __syncthreads();
    int f = tid;
    float4 wc = *(const float4*)&g_Wc[f * 4];
    float p[Nn];
    #pragma unroll
    for (int j = 0; j < Nn; j++) {
        p[j] = g_table2[scls[j] * Ff + f]
             + wc.x * sbb[j][0] + wc.y * sbb[j][1]
             + wc.z * sbb[j][2] + wc.w * sbb[j][3];
    }
    float n1[Nn];
    #pragma unroll
    for (int i = 0; i < Nn; i++) {
        float s = 0.f;
        #pragma unroll
        for (int j = 0; j < Nn; j++) s = fmaf(em[i][j], p[j], s);
        n1[i] = fmaxf(s, 0.f);
    }
    #pragma unroll
    for (int i = 0; i < Nn; i++) {
        float s = 0.f;
        #pragma unroll
        for (int j = 0; j < Nn; j++) s = fmaf(em[i][j], n1[j], s);
        g_Y[((size_t)bt * Nn + i) * Ff + f] = tf32r(s);
    }
}

// ---------------- tf32 mma.sync GEMM: C[M,512] = op(A[M,K] @ Bw[512,K]^T) ----
// BM=128, BN=128, BK=32; 256 thr = 8 warps (2 M x 4 N), warp tile 64x32.
// Grid: blockIdx.x = n-block (4, fastest), blockIdx.y = m-block -> the 4 CTAs
// sharing an A panel co-reside, so the A panel is fetched to L2 once (4x less
// DRAM A-traffic). Double-buffered cp.async; smem stride 36 words.
// RELU_CVT=1: relu + tf32-round epilogue (GEMM1). 0: plain store (GEMM2).
template<int RELU_CVT>
__global__ void __launch_bounds__(256, 2)
mgemm(const float* __restrict__ A, const float* __restrict__ Bw,
      float* __restrict__ C, int K) {
    constexpr int LDSW = 36;                    // words per smem row
    constexpr int SW   = 2 * 128 * LDSW;        // words per stage (A+B) = 9216
    extern __shared__ float sm[];
    const uint32_t smb = smem_u32(sm);
    const uint32_t* __restrict__ smu = (const uint32_t*)sm;

    int tid = threadIdx.x;
    int wid = tid >> 5, lane = tid & 31;
    int g = lane >> 2, t4 = lane & 3;
    int wm = wid & 1, wn = wid >> 1;            // 2 x 4 warp grid
    size_t m0 = (size_t)blockIdx.y * 128;       // m-block: slow index
    size_t n0 = (size_t)blockIdx.x * 128;       // n-block: fast index (L2 reuse)
    const float* Ab = A + m0 * (size_t)K;
    const float* Bb = Bw + n0 * (size_t)K;

    int nk = K >> 5;
    int lrow = tid >> 3, lc = (tid & 7) * 4;    // loader: row 0..31 base, col

    float acc[4][4][4];
    #pragma unroll
    for (int i = 0; i < 4; i++)
        #pragma unroll
        for (int j = 0; j < 4; j++)
            #pragma unroll
            for (int q = 0; q < 4; q++) acc[i][j][q] = 0.f;

    auto load_stage = [&](int s, int kt) {
        uint32_t base = smb + (uint32_t)s * SW * 4;
        size_t kof = (size_t)kt * 32;
        #pragma unroll
        for (int i = 0; i < 4; i++) {
            int row = lrow + i * 32;
            cpa16(base + (row * LDSW + lc) * 4, Ab + (size_t)row * K + kof + lc);
        }
        uint32_t bbase = base + 128 * LDSW * 4;
        #pragma unroll
        for (int i = 0; i < 4; i++) {
            int row = lrow + i * 32;
            cpa16(bbase + (row * LDSW + lc) * 4, Bb + (size_t)row * K + kof + lc);
        }
    };

    load_stage(0, 0);
    asm volatile("cp.async.commit_group;" ::: "memory");

    for (int kt = 0; kt < nk; kt++) {
        if (kt + 1 < nk) {
            load_stage((kt + 1) & 1, kt + 1);
            asm volatile("cp.async.commit_group;" ::: "memory");
            asm volatile("cp.async.wait_group 1;" ::: "memory");
        } else {
            asm volatile("cp.async.wait_group 0;" ::: "memory");
        }
        __syncthreads();

        const uint32_t* Su = smu + (kt & 1) * SW;
        const uint32_t* Bu = Su + 128 * LDSW;
        #pragma unroll
        for (int kk = 0; kk < 32; kk += 8) {
            uint32_t a[4][4], bfr[4][2];
            int ac = kk + t4;
            #pragma unroll
            for (int mt = 0; mt < 4; mt++) {
                int r = wm * 64 + mt * 16 + g;
                a[mt][0] = Su[r * LDSW + ac];
                a[mt][1] = Su[(r + 8) * LDSW + ac];
                a[mt][2] = Su[r * LDSW + ac + 4];
                a[mt][3] = Su[(r + 8) * LDSW + ac + 4];
            }
            #pragma unroll
            for (int nt = 0; nt < 4; nt++) {
                int r = wn * 32 + nt * 8 + g;
                bfr[nt][0] = Bu[r * LDSW + ac];
                bfr[nt][1] = Bu[r * LDSW + ac + 4];
            }
            #pragma unroll
            for (int mt = 0; mt < 4; mt++)
                #pragma unroll
                for (int nt = 0; nt < 4; nt++)
                    mma_tf32(acc[mt][nt], a[mt], bfr[nt]);
        }
        __syncthreads();
    }

    // ---- epilogue ----
    #pragma unroll
    for (int mt = 0; mt < 4; mt++) {
        #pragma unroll
        for (int nt = 0; nt < 4; nt++) {
            size_t row = m0 + wm * 64 + mt * 16 + g;
            size_t col = n0 + wn * 32 + nt * 8 + t4 * 2;
            float v0 = acc[mt][nt][0], v1 = acc[mt][nt][1];
            float v2 = acc[mt][nt][2], v3 = acc[mt][nt][3];
            if (RELU_CVT) {
                v0 = tf32r(fmaxf(v0, 0.f)); v1 = tf32r(fmaxf(v1, 0.f));
                v2 = tf32r(fmaxf(v2, 0.f)); v3 = tf32r(fmaxf(v3, 0.f));
            }
            *(float2*)&C[row * 512 + col]       = make_float2(v0, v1);
            *(float2*)&C[(row + 8) * 512 + col] = make_float2(v2, v3);
        }
    }
}

// ---------------- LayerNorm over F + transpose to [B,F,T] --------------------
__global__ void kln(const float* __restrict__ lnw, const float* __restrict__ lnb,
                    float* __restrict__ out) {
    int bt = blockIdx.x;
    int b = bt >> 11, t = bt & (Tt - 1);
    int tid = threadIdx.x;   // 256
    float v0 = g_feat[(size_t)bt * Ff + tid];
    float v1 = g_feat[(size_t)bt * Ff + 256 + tid];
    __shared__ float red[16];
    float s = v0 + v1;
    #pragma unroll
    for (int o = 16; o > 0; o >>= 1) s += __shfl_xor_sync(0xffffffffu, s, o);
    if ((tid & 31) == 0) red[tid >> 5] = s;
    __syncthreads();
    float mu = (red[0] + red[1] + red[2] + red[3] +
                red[4] + red[5] + red[6] + red[7]) * (1.f / Ff);
    float r0 = v0 - mu, r1 = v1 - mu;
    float q = r0 * r0 + r1 * r1;
    #pragma unroll
    for (int o = 16; o > 0; o >>= 1) q += __shfl_xor_sync(0xffffffffu, q, o);
    if ((tid & 31) == 0) red[8 + (tid >> 5)] = q;
    __syncthreads();
    float var = (red[8] + red[9] + red[10] + red[11] +
                 red[12] + red[13] + red[14] + red[15]) * (1.f / Ff);
    float inv = rsqrtf(var + 1e-5f);
    out[((size_t)b * Ff + tid) * Tt + t]       = r0 * inv * lnw[tid] + lnb[tid];
    out[((size_t)b * Ff + tid + 256) * Tt + t] = r1 * inv * lnw[tid + 256] + lnb[tid + 256];
}

// ---------------- launch ------------------------------------------------------
extern "C" void kernel_launch(void* const* d_in, const int* in_sizes, int n_in,
                              void* d_out, int out_size) {
    const float* bbox = (const float*)d_in[0];
    const int*   cls  = (const int*)d_in[1];
    const float* edge = (const float*)d_in[2];
    const float* Wlin = (const float*)d_in[3];
    const float* emb  = (const float*)d_in[4];
    const float* W1   = (const float*)d_in[5];
    const float* W2   = (const float*)d_in[6];
    const float* Wm   = (const float*)d_in[7];
    const float* lnw  = (const float*)d_in[8];
    const float* lnb  = (const float*)d_in[9];
    float* out = (float*)d_out;

    void *pY, *pN2, *pF, *pWm2, *pW2r;
    cudaGetSymbolAddress(&pY, g_Y);
    cudaGetSymbolAddress(&pN2, g_node2);
    cudaGetSymbolAddress(&pF, g_feat);
    cudaGetSymbolAddress(&pWm2, g_Wm2);
    cudaGetSymbolAddress(&pW2r, g_W2r);

    const int SMEMSZ = 2 * 2 * 128 * 36 * 4;   // 73728 B
    cudaFuncSetAttribute(mgemm<1>, cudaFuncAttributeMaxDynamicSharedMemorySize, SMEMSZ);
    cudaFuncSetAttribute(mgemm<0>, cudaFuncAttributeMaxDynamicSharedMemorySize, SMEMSZ);

    kprep<<<NC + 1, Ff>>>(W1, emb, Wlin);
    ktrans<<<(Ff * Nn * Ff) / 1024, 1024>>>(Wm);
    kw2<<<(Ff * Ff) / 1024, 1024>>>(W2);
    k1<<<BT, 512>>>(bbox, cls, edge);
    // GEMM1: node2 = tf32(relu(Y @ W2r^T))   [131072 x 512] x [512 x 512]
    // grid: (n-blocks=4, m-blocks=1024) -> n fastest for A-panel L2 reuse
    mgemm<1><<<dim3(Ff / 128, (BT * Nn) / 128), 256, SMEMSZ>>>(
        (const float*)pY, (const float*)pW2r, (float*)pN2, Ff);
    // GEMM2: feat = node2 @ Wm2^T            [8192 x 8192] x [512 x 8192]
    mgemm<0><<<dim3(Ff / 128, BT / 128), 256, SMEMSZ>>>(
        (const float*)pN2, (const float*)pWm2, (float*)pF, Nn * Ff);
    kln<<<BT, 256>>>(lnw, lnb, out);
}

// round 7
// speedup vs baseline: 1.2042x; 1.2042x over previous
#include <cuda_runtime.h>
#include <cuda_fp16.h>
#include <cstdint>

namespace {
constexpr int Bb = 4, Nn = 16, Tt = 2048, Ff = 512, NC = 43;
constexpr int BT = Bb * Tt;  // 8192
}

// ---------------- scratch (device globals; no allocation allowed) ------------
__device__ float  g_table2[NC * Ff];
__device__ float  g_Wc[Ff * 4];
__device__ __half g_W2h[Ff * Ff];                    // fp16 W2
__device__ __half g_Wm2h[Ff * Nn * Ff];              // fp16 Wm^T [f][n][c]
__device__ __half g_Yh[(long long)BT * Nn * Ff];     // 128MB
__device__ __half g_node2h[(long long)BT * Nn * Ff]; // 128MB
__device__ float  g_feat[(long long)BT * Ff];        // 16MB

// ---------------- helpers -----------------------------------------------------
__device__ __forceinline__ uint32_t smem_u32(const void* p) {
    uint32_t a;
    asm("{ .reg .u64 t; cvta.to.shared.u64 t, %1; cvt.u32.u64 %0, t; }" : "=r"(a) : "l"(p));
    return a;
}
__device__ __forceinline__ void cpa16(uint32_t s, const void* g) {
    asm volatile("cp.async.cg.shared.global [%0], [%1], 16;" :: "r"(s), "l"(g) : "memory");
}
// f16-accumulator mma (2x rate vs f32acc) with immediate fp32 promotion.
// Error stays fp32-class: f16 rounding only inside one k16 dot.
__device__ __forceinline__ void mma_f16acc(float* c, const uint32_t* a, const uint32_t* b) {
    uint32_t d0, d1;
    asm volatile(
        "mma.sync.aligned.m16n8k16.row.col.f16.f16.f16.f16 "
        "{%0,%1}, {%2,%3,%4,%5}, {%6,%7}, {%8,%8};"
        : "=r"(d0), "=r"(d1)
        : "r"(a[0]), "r"(a[1]), "r"(a[2]), "r"(a[3]), "r"(b[0]), "r"(b[1]),
          "r"(0u));
    float2 lo = __half22float2(*reinterpret_cast<__half2*>(&d0));
    float2 hi = __half22float2(*reinterpret_cast<__half2*>(&d1));
    c[0] += lo.x; c[1] += lo.y; c[2] += hi.x; c[3] += hi.y;
}

// ---------------- precompute: table2 = W1a@emb^T, Wc = W1b@W_lin -------------
__global__ void kprep(const float* __restrict__ W1, const float* __restrict__ emb,
                      const float* __restrict__ Wlin) {
    __shared__ float se[Ff];
    __shared__ float sw[Ff * 4];
    int f = threadIdx.x;
    int c = blockIdx.x;
    if (c < NC) {
        se[f] = emb[c * Ff + f];
        __syncthreads();
        float s = 0.f;
        const float* w = W1 + (size_t)f * (2 * Ff);
        #pragma unroll 8
        for (int k = 0; k < Ff; k++) s = fmaf(w[k], se[k], s);
        g_table2[c * Ff + f] = s;
    } else {
        #pragma unroll
        for (int q = 0; q < 4; q++) sw[f + q * Ff] = Wlin[f + q * Ff];
        __syncthreads();
        float s0 = 0.f, s1 = 0.f, s2 = 0.f, s3 = 0.f;
        const float* w = W1 + (size_t)f * (2 * Ff) + Ff;
        #pragma unroll 4
        for (int k = 0; k < Ff; k++) {
            float v = w[k];
            s0 = fmaf(v, sw[k * 4 + 0], s0);
            s1 = fmaf(v, sw[k * 4 + 1], s1);
            s2 = fmaf(v, sw[k * 4 + 2], s2);
            s3 = fmaf(v, sw[k * 4 + 3], s3);
        }
        g_Wc[f * 4 + 0] = s0; g_Wc[f * 4 + 1] = s1;
        g_Wc[f * 4 + 2] = s2; g_Wc[f * 4 + 3] = s3;
    }
}

// ---------------- precompute: Wm2h[f][n][c] = h(Wm[f][c][n]), W2h = h(W2) ----
__global__ void ktrans(const float* __restrict__ Wm) {
    int idx = blockIdx.x * 1024 + threadIdx.x;
    int c = idx & (Ff - 1);
    int n = (idx >> 9) & (Nn - 1);
    int f = idx >> 13;
    g_Wm2h[idx] = __float2half_rn(Wm[((size_t)f * Ff + c) * Nn + n]);
}
__global__ void kw2(const float* __restrict__ W2) {
    int i = blockIdx.x * 1024 + threadIdx.x;
    g_W2h[i] = __float2half_rn(W2[i]);
}

// ---------------- stage 1: lookups + two 16x16 em matmuls -> Yh (fp16) -------
__global__ void __launch_bounds__(512, 3)
k1(const float* __restrict__ bbox, const int* __restrict__ cls,
   const float* __restrict__ edge) {
    int bt = blockIdx.x;
    int b = bt >> 11, t = bt & (Tt - 1);
    __shared__ float em[Nn][Nn];
    __shared__ int   scls[Nn];
    __shared__ float sbb[Nn][4];
    int tid = threadIdx.x;   // 512
    if (tid < 256) {
        int i = tid >> 4, j = tid & 15;
        em[i][j] = edge[((size_t)(b * Nn + i) * Nn + j) * Tt + t];
    }
    if (tid >= 256 && tid < 256 + Nn)
        scls[tid - 256] = cls[(size_t)(b * Nn + tid - 256) * Tt + t];
    if (tid >= 320 && tid < 320 + Nn * 4) {
        int q = tid - 320;
        int j = q >> 2, c = q & 3;
        sbb[j][c] = bbox[((size_t)(b * Nn + j) * 4 + c) * Tt + t];
    }
    __syncthreads();
    int f = tid;
    float4 wc = *(const float4*)&g_Wc[f * 4];
    float p[Nn];
    #pragma unroll
    for (int j = 0; j < Nn; j++) {
        p[j] = g_table2[scls[j] * Ff + f]
             + wc.x * sbb[j][0] + wc.y * sbb[j][1]
             + wc.z * sbb[j][2] + wc.w * sbb[j][3];
    }
    float n1[Nn];
    #pragma unroll
    for (int i = 0; i < Nn; i++) {
        float s = 0.f;
        #pragma unroll
        for (int j = 0; j < Nn; j++) s = fmaf(em[i][j], p[j], s);
        n1[i] = fmaxf(s, 0.f);
    }
    #pragma unroll
    for (int i = 0; i < Nn; i++) {
        float s = 0.f;
        #pragma unroll
        for (int j = 0; j < Nn; j++) s = fmaf(em[i][j], n1[j], s);
        g_Yh[((size_t)bt * Nn + i) * Ff + f] = __float2half_rn(s);
    }
}

// ---------------- fp16 mma GEMM (f16acc + fp32 promote): ---------------------
// C = op(A[M,K]h @ Bw[512,K]h^T). BM=128, BN=128, BK=32 halves; 256 thr =
// 8 warps (2M x 4N), warp tile 64x32. SMEM rows padded to 40 halves.
// RELU=1: relu -> half store (GEMM1). RELU=0: fp32 store (GEMM2).
template<int RELU>
__global__ void __launch_bounds__(256, 2)
hgemm(const __half* __restrict__ A, const __half* __restrict__ Bw,
      void* __restrict__ Cout, int K) {
    constexpr int LDW = 20;                     // words per smem row (40 halves)
    constexpr int TILE_W = 128 * LDW;           // words per A (or B) tile = 2560
    constexpr int STG_W = 2 * TILE_W;           // words per stage = 5120
    extern __shared__ uint32_t sm[];
    const uint32_t smb = smem_u32(sm);

    int tid = threadIdx.x;
    int wid = tid >> 5, lane = tid & 31;
    int g = lane >> 2, t4 = lane & 3;
    int wm = wid & 1, wn = wid >> 1;
    size_t m0 = (size_t)blockIdx.x * 128;
    size_t n0 = (size_t)blockIdx.y * 128;
    const __half* Ab = A + m0 * (size_t)K;
    const __half* Bb = Bw + n0 * (size_t)K;
    int nk = K >> 5;
    int lrow = tid >> 2, lc = tid & 3;          // loader: 64 rows/pass, 4 chunks

    float acc[4][4][4];
    #pragma unroll
    for (int i = 0; i < 4; i++)
        #pragma unroll
        for (int j = 0; j < 4; j++)
            #pragma unroll
            for (int q = 0; q < 4; q++) acc[i][j][q] = 0.f;

    auto load_stage = [&](int s, int kt) {
        uint32_t base = smb + (uint32_t)s * STG_W * 4;
        size_t kof = (size_t)kt * 32;
        #pragma unroll
        for (int i = 0; i < 2; i++) {
            int r = lrow + i * 64;
            cpa16(base + (r * LDW + lc * 4) * 4,
                  Ab + (size_t)r * K + kof + lc * 8);
            cpa16(base + TILE_W * 4 + (r * LDW + lc * 4) * 4,
                  Bb + (size_t)r * K + kof + lc * 8);
        }
    };

    load_stage(0, 0);
    asm volatile("cp.async.commit_group;" ::: "memory");

    for (int kt = 0; kt < nk; kt++) {
        if (kt + 1 < nk) {
            load_stage((kt + 1) & 1, kt + 1);
            asm volatile("cp.async.commit_group;" ::: "memory");
            asm volatile("cp.async.wait_group 1;" ::: "memory");
        } else {
            asm volatile("cp.async.wait_group 0;" ::: "memory");
        }
        __syncthreads();

        const uint32_t* Su = sm + (kt & 1) * STG_W;
        const uint32_t* Bu = Su + TILE_W;
        #pragma unroll
        for (int kk = 0; kk < 2; kk++) {         // two k16 steps
            int ac = kk * 8 + t4;
            uint32_t a[4][4], bf[4][2];
            #pragma unroll
            for (int mt = 0; mt < 4; mt++) {
                int r = wm * 64 + mt * 16 + g;
                a[mt][0] = Su[r * LDW + ac];
                a[mt][1] = Su[(r + 8) * LDW + ac];
                a[mt][2] = Su[r * LDW + ac + 4];
                a[mt][3] = Su[(r + 8) * LDW + ac + 4];
            }
            #pragma unroll
            for (int nt = 0; nt < 4; nt++) {
                int r = wn * 32 + nt * 8 + g;
                bf[nt][0] = Bu[r * LDW + ac];
                bf[nt][1] = Bu[r * LDW + ac + 4];
            }
            #pragma unroll
            for (int mt = 0; mt < 4; mt++)
                #pragma unroll
                for (int nt = 0; nt < 4; nt++)
                    mma_f16acc(acc[mt][nt], a[mt], bf[nt]);
        }
        __syncthreads();
    }

    // ---- epilogue ----
    #pragma unroll
    for (int mt = 0; mt < 4; mt++) {
        #pragma unroll
        for (int nt = 0; nt < 4; nt++) {
            size_t row = m0 + wm * 64 + mt * 16 + g;
            size_t col = n0 + wn * 32 + nt * 8 + t4 * 2;
            float* c = acc[mt][nt];
            if (RELU) {
                __half* Ch = (__half*)Cout;
                __half2 h0 = __floats2half2_rn(fmaxf(c[0], 0.f), fmaxf(c[1], 0.f));
                __half2 h1 = __floats2half2_rn(fmaxf(c[2], 0.f), fmaxf(c[3], 0.f));
                *(__half2*)&Ch[row * 512 + col]       = h0;
                *(__half2*)&Ch[(row + 8) * 512 + col] = h1;
            } else {
                float* Cf = (float*)Cout;
                *(float2*)&Cf[row * 512 + col]       = make_float2(c[0], c[1]);
                *(float2*)&Cf[(row + 8) * 512 + col] = make_float2(c[2], c[3]);
            }
        }
    }
}

// ---------------- LayerNorm over F + transpose to [B,F,T] --------------------
__global__ void kln(const float* __restrict__ lnw, const float* __restrict__ lnb,
                    float* __restrict__ out) {
    int bt = blockIdx.x;
    int b = bt >> 11, t = bt & (Tt - 1);
    int tid = threadIdx.x;   // 256
    float v0 = g_feat[(size_t)bt * Ff + tid];
    float v1 = g_feat[(size_t)bt * Ff + 256 + tid];
    __shared__ float red[16];
    float s = v0 + v1;
    #pragma unroll
    for (int o = 16; o > 0; o >>= 1) s += __shfl_xor_sync(0xffffffffu, s, o);
    if ((tid & 31) == 0) red[tid >> 5] = s;
    __syncthreads();
    float mu = (red[0] + red[1] + red[2] + red[3] +
                red[4] + red[5] + red[6] + red[7]) * (1.f / Ff);
    float r0 = v0 - mu, r1 = v1 - mu;
    float q = r0 * r0 + r1 * r1;
    #pragma unroll
    for (int o = 16; o > 0; o >>= 1) q += __shfl_xor_sync(0xffffffffu, q, o);
    if ((tid & 31) == 0) red[8 + (tid >> 5)] = q;
    __syncthreads();
    float var = (red[8] + red[9] + red[10] + red[11] +
                 red[12] + red[13] + red[14] + red[15]) * (1.f / Ff);
    float inv = rsqrtf(var + 1e-5f);
    out[((size_t)b * Ff + tid) * Tt + t]       = r0 * inv * lnw[tid] + lnb[tid];
    out[((size_t)b * Ff + tid + 256) * Tt + t] = r1 * inv * lnw[tid + 256] + lnb[tid + 256];
}

// ---------------- launch ------------------------------------------------------
extern "C" void kernel_launch(void* const* d_in, const int* in_sizes, int n_in,
                              void* d_out, int out_size) {
    const float* bbox = (const float*)d_in[0];
    const int*   cls  = (const int*)d_in[1];
    const float* edge = (const float*)d_in[2];
    const float* Wlin = (const float*)d_in[3];
    const float* emb  = (const float*)d_in[4];
    const float* W1   = (const float*)d_in[5];
    const float* W2   = (const float*)d_in[6];
    const float* Wm   = (const float*)d_in[7];
    const float* lnw  = (const float*)d_in[8];
    const float* lnb  = (const float*)d_in[9];
    float* out = (float*)d_out;

    void *pY, *pN2, *pF, *pWm2, *pW2;
    cudaGetSymbolAddress(&pY, g_Yh);
    cudaGetSymbolAddress(&pN2, g_node2h);
    cudaGetSymbolAddress(&pF, g_feat);
    cudaGetSymbolAddress(&pWm2, g_Wm2h);
    cudaGetSymbolAddress(&pW2, g_W2h);

    const int SMEMSZ = 2 * 2 * 128 * 20 * 4;   // 40960 B
    cudaFuncSetAttribute(hgemm<1>, cudaFuncAttributeMaxDynamicSharedMemorySize, SMEMSZ);
    cudaFuncSetAttribute(hgemm<0>, cudaFuncAttributeMaxDynamicSharedMemorySize, SMEMSZ);

    kprep<<<NC + 1, Ff>>>(W1, emb, Wlin);
    ktrans<<<(Ff * Nn * Ff) / 1024, 1024>>>(Wm);
    kw2<<<(Ff * Ff) / 1024, 1024>>>(W2);
    k1<<<BT, 512>>>(bbox, cls, edge);
    // GEMM1: node2h = h(relu(Yh @ W2h^T))   [131072 x 512] x [512 x 512]
    hgemm<1><<<dim3((BT * Nn) / 128, Ff / 128), 256, SMEMSZ>>>(
        (const __half*)pY, (const __half*)pW2, pN2, Ff);
    // GEMM2: feat = node2h @ Wm2h^T         [8192 x 8192] x [512 x 8192]
    hgemm<0><<<dim3(BT / 128, Ff / 128), 256, SMEMSZ>>>(
        (const __half*)pN2, (const __half*)pWm2, pF, Nn * Ff);
    kln<<<BT, 256>>>(lnw, lnb, out);
}

// round 8
// speedup vs baseline: 1.3427x; 1.1150x over previous
#include <cuda_runtime.h>
#include <cuda_fp16.h>
#include <cstdint>

namespace {
constexpr int Bb = 4, Nn = 16, Tt = 2048, Ff = 512, NC = 43;
constexpr int BT = Bb * Tt;  // 8192
}

// ---------------- scratch (device globals; no allocation allowed) ------------
__device__ float  g_table2[NC * Ff];
__device__ float  g_Wc[Ff * 4];
__device__ __half g_W2h[Ff * Ff];                    // fp16 W2
__device__ __half g_Wm2h[Ff * Nn * Ff];              // fp16 Wm^T [f][n][c]
__device__ __half g_Yh[(long long)BT * Nn * Ff];     // 128MB
__device__ __half g_node2h[(long long)BT * Nn * Ff]; // 128MB
__device__ float  g_feat[(long long)BT * Ff];        // 16MB

// ---------------- helpers -----------------------------------------------------
__device__ __forceinline__ uint32_t smem_u32(const void* p) {
    uint32_t a;
    asm("{ .reg .u64 t; cvta.to.shared.u64 t, %1; cvt.u32.u64 %0, t; }" : "=r"(a) : "l"(p));
    return a;
}
__device__ __forceinline__ void cpa16(uint32_t s, const void* g) {
    asm volatile("cp.async.cg.shared.global [%0], [%1], 16;" :: "r"(s), "l"(g) : "memory");
}
__device__ __forceinline__ void ldsm4(uint32_t* r, uint32_t addr) {
    asm volatile("ldmatrix.sync.aligned.m8n8.x4.shared.b16 {%0,%1,%2,%3}, [%4];"
                 : "=r"(r[0]), "=r"(r[1]), "=r"(r[2]), "=r"(r[3]) : "r"(addr));
}
__device__ __forceinline__ void mma_f16(float* c, const uint32_t* a, const uint32_t* b) {
    asm volatile(
        "mma.sync.aligned.m16n8k16.row.col.f32.f16.f16.f32 "
        "{%0,%1,%2,%3}, {%4,%5,%6,%7}, {%8,%9}, {%0,%1,%2,%3};"
        : "+f"(c[0]), "+f"(c[1]), "+f"(c[2]), "+f"(c[3])
        : "r"(a[0]), "r"(a[1]), "r"(a[2]), "r"(a[3]), "r"(b[0]), "r"(b[1]));
}

// ---------------- precompute: table2 = W1a@emb^T, Wc = W1b@W_lin -------------
__global__ void kprep(const float* __restrict__ W1, const float* __restrict__ emb,
                      const float* __restrict__ Wlin) {
    __shared__ float se[Ff];
    __shared__ float sw[Ff * 4];
    int f = threadIdx.x;
    int c = blockIdx.x;
    if (c < NC) {
        se[f] = emb[c * Ff + f];
        __syncthreads();
        float s = 0.f;
        const float* w = W1 + (size_t)f * (2 * Ff);
        #pragma unroll 8
        for (int k = 0; k < Ff; k++) s = fmaf(w[k], se[k], s);
        g_table2[c * Ff + f] = s;
    } else {
        #pragma unroll
        for (int q = 0; q < 4; q++) sw[f + q * Ff] = Wlin[f + q * Ff];
        __syncthreads();
        float s0 = 0.f, s1 = 0.f, s2 = 0.f, s3 = 0.f;
        const float* w = W1 + (size_t)f * (2 * Ff) + Ff;
        #pragma unroll 4
        for (int k = 0; k < Ff; k++) {
            float v = w[k];
            s0 = fmaf(v, sw[k * 4 + 0], s0);
            s1 = fmaf(v, sw[k * 4 + 1], s1);
            s2 = fmaf(v, sw[k * 4 + 2], s2);
            s3 = fmaf(v, sw[k * 4 + 3], s3);
        }
        g_Wc[f * 4 + 0] = s0; g_Wc[f * 4 + 1] = s1;
        g_Wc[f * 4 + 2] = s2; g_Wc[f * 4 + 3] = s3;
    }
}

// ---------------- precompute: Wm2h[f][n][c] = h(Wm[f][c][n]), W2h = h(W2) ----
__global__ void ktrans(const float* __restrict__ Wm) {
    int idx = blockIdx.x * 1024 + threadIdx.x;
    int c = idx & (Ff - 1);
    int n = (idx >> 9) & (Nn - 1);
    int f = idx >> 13;
    g_Wm2h[idx] = __float2half_rn(Wm[((size_t)f * Ff + c) * Nn + n]);
}
__global__ void kw2(const float* __restrict__ W2) {
    int i = blockIdx.x * 1024 + threadIdx.x;
    g_W2h[i] = __float2half_rn(W2[i]);
}

// ---------------- stage 1: lookups + two 16x16 em matmuls -> Yh (fp16) -------
__global__ void __launch_bounds__(512, 3)
k1(const float* __restrict__ bbox, const int* __restrict__ cls,
   const float* __restrict__ edge) {
    int bt = blockIdx.x;
    int b = bt >> 11, t = bt & (Tt - 1);
    __shared__ float em[Nn][Nn];
    __shared__ int   scls[Nn];
    __shared__ float sbb[Nn][4];
    int tid = threadIdx.x;   // 512
    if (tid < 256) {
        int i = tid >> 4, j = tid & 15;
        em[i][j] = edge[((size_t)(b * Nn + i) * Nn + j) * Tt + t];
    }
    if (tid >= 256 && tid < 256 + Nn)
        scls[tid - 256] = cls[(size_t)(b * Nn + tid - 256) * Tt + t];
    if (tid >= 320 && tid < 320 + Nn * 4) {
        int q = tid - 320;
        int j = q >> 2, c = q & 3;
        sbb[j][c] = bbox[((size_t)(b * Nn + j) * 4 + c) * Tt + t];
    }
    __syncthreads();
    int f = tid;
    float4 wc = *(const float4*)&g_Wc[f * 4];
    float p[Nn];
    #pragma unroll
    for (int j = 0; j < Nn; j++) {
        p[j] = g_table2[scls[j] * Ff + f]
             + wc.x * sbb[j][0] + wc.y * sbb[j][1]
             + wc.z * sbb[j][2] + wc.w * sbb[j][3];
    }
    float n1[Nn];
    #pragma unroll
    for (int i = 0; i < Nn; i++) {
        float s = 0.f;
        #pragma unroll
        for (int j = 0; j < Nn; j++) s = fmaf(em[i][j], p[j], s);
        n1[i] = fmaxf(s, 0.f);
    }
    #pragma unroll
    for (int i = 0; i < Nn; i++) {
        float s = 0.f;
        #pragma unroll
        for (int j = 0; j < Nn; j++) s = fmaf(em[i][j], n1[j], s);
        g_Yh[((size_t)bt * Nn + i) * Ff + f] = __float2half_rn(s);
    }
}

// ---------------- fp16 mma GEMM v2: ldmatrix + BK=64 + 3-stage ring ----------
// C = op(A[M,K]h @ Bw[512,K]h^T). BM=128, BN=128, BK=64 halves; 256 thr =
// 8 warps (2M x 4N), warp tile 64x32. SMEM rows: 64 halves + 8 pad = 144B.
// RELU=1: relu -> half store (GEMM1). RELU=0: fp32 store (GEMM2).
template<int RELU>
__global__ void __launch_bounds__(256, 2)
hgemm(const __half* __restrict__ A, const __half* __restrict__ Bw,
      void* __restrict__ Cout, int K) {
    constexpr int ROWB   = 144;                 // bytes per smem row
    constexpr int TILE_B = 128 * ROWB;          // 18432 B per A (or B) tile
    constexpr int STG_B  = 2 * TILE_B;          // 36864 B per stage
    extern __shared__ char sm[];
    const uint32_t smb = smem_u32(sm);

    int tid = threadIdx.x;
    int wid = tid >> 5, lane = tid & 31;
    int g = lane >> 2, t4 = lane & 3;
    int wm = wid & 1, wn = wid >> 1;
    size_t m0 = (size_t)blockIdx.x * 128;
    size_t n0 = (size_t)blockIdx.y * 128;
    const __half* Ab = A + m0 * (size_t)K;
    const __half* Bb = Bw + n0 * (size_t)K;
    int nk = K >> 6;                            // stages of 64 halves

    // ldmatrix lane-row offsets (within-stage byte offsets, before +stage base)
    int lrow16 = lane & 15;
    int lk8    = (lane >> 4) << 3;              // 0 or 8 halves
    uint32_t offA[4], offB[2];
    #pragma unroll
    for (int mt = 0; mt < 4; mt++)
        offA[mt] = (uint32_t)((wm * 64 + mt * 16 + lrow16) * ROWB + lk8 * 2);
    #pragma unroll
    for (int p = 0; p < 2; p++)
        offB[p] = (uint32_t)(TILE_B + (wn * 32 + p * 16 + lrow16) * ROWB + lk8 * 2);

    float acc[4][4][4];
    #pragma unroll
    for (int i = 0; i < 4; i++)
        #pragma unroll
        for (int j = 0; j < 4; j++)
            #pragma unroll
            for (int q = 0; q < 4; q++) acc[i][j][q] = 0.f;

    // loader: A 128x64h + B 128x64h per stage; 2048 cpa16 / 256 thr = 8 each
    int lrow = tid >> 3, lc = tid & 7;          // row base 0..31, 16B chunk
    auto load_stage = [&](int s, int kt) {
        uint32_t base = smb + (uint32_t)s * STG_B;
        size_t kof = (size_t)kt * 64;
        #pragma unroll
        for (int i = 0; i < 4; i++) {
            int r = lrow + i * 32;
            cpa16(base + r * ROWB + lc * 16, Ab + (size_t)r * K + kof + lc * 8);
            cpa16(base + TILE_B + r * ROWB + lc * 16,
                  Bb + (size_t)r * K + kof + lc * 8);
        }
    };

    load_stage(0, 0);
    asm volatile("cp.async.commit_group;" ::: "memory");
    if (nk > 1) load_stage(1, 1);
    asm volatile("cp.async.commit_group;" ::: "memory");

    for (int kt = 0; kt < nk; kt++) {
        if (kt + 2 < nk) {
            asm volatile("cp.async.wait_group 1;" ::: "memory");
        } else {
            asm volatile("cp.async.wait_group 0;" ::: "memory");
        }
        __syncthreads();
        // prefetch kt+2 into ring slot (kt+2)%3 (safe: its readers done)
        if (kt + 2 < nk) {
            load_stage((kt + 2) % 3, kt + 2);
            asm volatile("cp.async.commit_group;" ::: "memory");
        }

        uint32_t sbase = smb + (uint32_t)(kt % 3) * STG_B;
        #pragma unroll
        for (int kk = 0; kk < 4; kk++) {         // four k16 steps
            uint32_t koff = (uint32_t)(kk * 32); // 16 halves = 32 B
            uint32_t a[4][4], bf[4][2];
            #pragma unroll
            for (int mt = 0; mt < 4; mt++)
                ldsm4(a[mt], sbase + offA[mt] + koff);
            #pragma unroll
            for (int p = 0; p < 2; p++) {
                uint32_t r[4];
                ldsm4(r, sbase + offB[p] + koff);
                bf[p * 2 + 0][0] = r[0]; bf[p * 2 + 0][1] = r[2];
                bf[p * 2 + 1][0] = r[1]; bf[p * 2 + 1][1] = r[3];
            }
            #pragma unroll
            for (int mt = 0; mt < 4; mt++)
                #pragma unroll
                for (int nt = 0; nt < 4; nt++)
                    mma_f16(acc[mt][nt], a[mt], bf[nt]);
        }
        __syncthreads();
    }

    // ---- epilogue ----
    #pragma unroll
    for (int mt = 0; mt < 4; mt++) {
        #pragma unroll
        for (int nt = 0; nt < 4; nt++) {
            size_t row = m0 + wm * 64 + mt * 16 + g;
            size_t col = n0 + wn * 32 + nt * 8 + t4 * 2;
            float* c = acc[mt][nt];
            if (RELU) {
                __half* Ch = (__half*)Cout;
                __half2 h0 = __floats2half2_rn(fmaxf(c[0], 0.f), fmaxf(c[1], 0.f));
                __half2 h1 = __floats2half2_rn(fmaxf(c[2], 0.f), fmaxf(c[3], 0.f));
                *(__half2*)&Ch[row * 512 + col]       = h0;
                *(__half2*)&Ch[(row + 8) * 512 + col] = h1;
            } else {
                float* Cf = (float*)Cout;
                *(float2*)&Cf[row * 512 + col]       = make_float2(c[0], c[1]);
                *(float2*)&Cf[(row + 8) * 512 + col] = make_float2(c[2], c[3]);
            }
        }
    }
}

// ---------------- LayerNorm over F + transpose to [B,F,T] --------------------
__global__ void kln(const float* __restrict__ lnw, const float* __restrict__ lnb,
                    float* __restrict__ out) {
    int bt = blockIdx.x;
    int b = bt >> 11, t = bt & (Tt - 1);
    int tid = threadIdx.x;   // 256
    float v0 = g_feat[(size_t)bt * Ff + tid];
    float v1 = g_feat[(size_t)bt * Ff + 256 + tid];
    __shared__ float red[16];
    float s = v0 + v1;
    #pragma unroll
    for (int o = 16; o > 0; o >>= 1) s += __shfl_xor_sync(0xffffffffu, s, o);
    if ((tid & 31) == 0) red[tid >> 5] = s;
    __syncthreads();
    float mu = (red[0] + red[1] + red[2] + red[3] +
                red[4] + red[5] + red[6] + red[7]) * (1.f / Ff);
    float r0 = v0 - mu, r1 = v1 - mu;
    float q = r0 * r0 + r1 * r1;
    #pragma unroll
    for (int o = 16; o > 0; o >>= 1) q += __shfl_xor_sync(0xffffffffu, q, o);
    if ((tid & 31) == 0) red[8 + (tid >> 5)] = q;
    __syncthreads();
    float var = (red[8] + red[9] + red[10] + red[11] +
                 red[12] + red[13] + red[14] + red[15]) * (1.f / Ff);
    float inv = rsqrtf(var + 1e-5f);
    out[((size_t)b * Ff + tid) * Tt + t]       = r0 * inv * lnw[tid] + lnb[tid];
    out[((size_t)b * Ff + tid + 256) * Tt + t] = r1 * inv * lnw[tid + 256] + lnb[tid + 256];
}

// ---------------- launch ------------------------------------------------------
extern "C" void kernel_launch(void* const* d_in, const int* in_sizes, int n_in,
                              void* d_out, int out_size) {
    const float* bbox = (const float*)d_in[0];
    const int*   cls  = (const int*)d_in[1];
    const float* edge = (const float*)d_in[2];
    const float* Wlin = (const float*)d_in[3];
    const float* emb  = (const float*)d_in[4];
    const float* W1   = (const float*)d_in[5];
    const float* W2   = (const float*)d_in[6];
    const float* Wm   = (const float*)d_in[7];
    const float* lnw  = (const float*)d_in[8];
    const float* lnb  = (const float*)d_in[9];
    float* out = (float*)d_out;

    void *pY, *pN2, *pF, *pWm2, *pW2;
    cudaGetSymbolAddress(&pY, g_Yh);
    cudaGetSymbolAddress(&pN2, g_node2h);
    cudaGetSymbolAddress(&pF, g_feat);
    cudaGetSymbolAddress(&pWm2, g_Wm2h);
    cudaGetSymbolAddress(&pW2, g_W2h);

    const int SMEMSZ = 3 * 2 * 128 * 144;      // 110592 B (3-stage ring)
    cudaFuncSetAttribute(hgemm<1>, cudaFuncAttributeMaxDynamicSharedMemorySize, SMEMSZ);
    cudaFuncSetAttribute(hgemm<0>, cudaFuncAttributeMaxDynamicSharedMemorySize, SMEMSZ);

    kprep<<<NC + 1, Ff>>>(W1, emb, Wlin);
    ktrans<<<(Ff * Nn * Ff) / 1024, 1024>>>(Wm);
    kw2<<<(Ff * Ff) / 1024, 1024>>>(W2);
    k1<<<BT, 512>>>(bbox, cls, edge);
    // GEMM1: node2h = h(relu(Yh @ W2h^T))   [131072 x 512] x [512 x 512]
    hgemm<1><<<dim3((BT * Nn) / 128, Ff / 128), 256, SMEMSZ>>>(
        (const __half*)pY, (const __half*)pW2, pN2, Ff);
    // GEMM2: feat = node2h @ Wm2h^T         [8192 x 8192] x [512 x 8192]
    hgemm<0><<<dim3(BT / 128, Ff / 128), 256, SMEMSZ>>>(
        (const __half*)pN2, (const __half*)pWm2, pF, Nn * Ff);
    kln<<<BT, 256>>>(lnw, lnb, out);
}